// round 13
// baseline (speedup 1.0000x reference)
#include <cuda_runtime.h>
#include <cstdint>

// out[row, t] = x[row, t - s]  if 0 <= t - s < T else 0
// rows = 256, T = 160000 (T % 4 == 0), s = shifts[row] - max_shift in [-16000, 16000]
//
// R13: TMA bulk-read experiment. Interior tiles stage their (16B-aligned)
// covering source window in SMEM via ONE cp.async.bulk (UBLKCP) transaction
// instead of ~4096 scalar LDGs, testing whether bulk contiguous reads improve
// DRAM burst/row-buffer efficiency past the ~74% plateau. Consumers read the
// row-uniformly misaligned window from SMEM and store aligned float4 (__stcs).
// Edge tiles use the proven R3 predicated global path.

#define VEC 4
#define THREADS 256
#define WPB (VEC * THREADS)            // 1024 float4 words = 4096 floats per tile
#define STAGE_BYTES (WPB * 16 + 16)    // covering window: 16400 B (16B multiple)

__device__ __forceinline__ uint32_t smem_u32(const void* p) {
    uint32_t a;
    asm("{ .reg .u64 t; cvta.to.shared.u64 t, %1; cvt.u32.u64 %0, t; }"
        : "=r"(a) : "l"(p));
    return a;
}

__global__ void __launch_bounds__(THREADS)
random_shift_kernel(const float* __restrict__ x,
                    const int* __restrict__ shifts,
                    float4* __restrict__ out4,
                    int T, int max_shift) {
    __shared__ __align__(128) float stage[STAGE_BYTES / 4];
    __shared__ __align__(8) unsigned long long mbar;

    const int row = blockIdx.y;
    const int s = shifts[row] - max_shift;

    const int T4 = T >> 2;
    const int tile0 = blockIdx.x * WPB;
    const size_t ebase = (size_t)row * (size_t)T;
    const size_t wbase = (size_t)row * (size_t)T4;
    const float* __restrict__ xr = x + ebase;

    const int src_lo = 4 * tile0 - s;                    // first source element
    const int src_hi = 4 * (tile0 + WPB) - s;            // one past last
    // need aligned window [g0, g0 + 4100) inside the row
    const bool interior = (src_lo >= 0) && (src_hi + 4 <= T) && (tile0 + WPB <= T4);

    if (interior) {
        const int g0   = src_lo & ~3;                    // 16B-aligned start elem
        const int aoff = src_lo & 3;                     // row-uniform, 0..3

        const uint32_t mb = smem_u32(&mbar);
        const uint32_t st = smem_u32(stage);

        if (threadIdx.x == 0) {
            asm volatile("mbarrier.init.shared.b64 [%0], 1;" :: "r"(mb) : "memory");
        }
        __syncthreads();
        if (threadIdx.x == 0) {
            asm volatile("mbarrier.arrive.expect_tx.shared.b64 _, [%0], %1;"
                         :: "r"(mb), "r"((uint32_t)STAGE_BYTES) : "memory");
            asm volatile(
                "cp.async.bulk.shared::cta.global.mbarrier::complete_tx::bytes "
                "[%0], [%1], %2, [%3];"
                :: "r"(st), "l"(xr + g0), "r"((uint32_t)STAGE_BYTES), "r"(mb)
                : "memory");
        }
        // all threads wait for the bulk copy (parity 0, single use)
        {
            uint32_t done;
            asm volatile(
                "{\n\t.reg .pred p;\n\t"
                "mbarrier.try_wait.parity.acquire.cta.shared::cta.b64 p, [%1], 0;\n\t"
                "selp.b32 %0, 1, 0, p;\n\t}"
                : "=r"(done) : "r"(mb) : "memory");
            if (!done) {
                asm volatile(
                    "{\n\t.reg .pred P1;\n\t"
                    "WL_%=:\n\t"
                    "mbarrier.try_wait.parity.acquire.cta.shared::cta.b64 P1, [%0], 0, 0x989680;\n\t"
                    "@P1 bra.uni WD_%=;\n\t"
                    "bra.uni WL_%=;\n\t"
                    "WD_%=:\n\t}"
                    :: "r"(mb) : "memory");
            }
        }

        // recombine from SMEM (misaligned by aoff floats, row-uniform) and store
        float4 v[VEC];
#pragma unroll
        for (int k = 0; k < VEC; ++k) {
            const int j = (int)threadIdx.x + k * THREADS;    // local word 0..1023
            const float* p = stage + 4 * j + aoff;
            v[k] = make_float4(p[0], p[1], p[2], p[3]);
        }
#pragma unroll
        for (int k = 0; k < VEC; ++k) {
            const int w = tile0 + (int)threadIdx.x + k * THREADS;
            __stcs(out4 + wbase + w, v[k]);
        }
    } else {
        float4 v[VEC];
#pragma unroll
        for (int k = 0; k < VEC; ++k) {
            const int w = tile0 + threadIdx.x + k * THREADS;
            const int u = 4 * w - s;
            float t0 = 0.f, t1 = 0.f, t2 = 0.f, t3 = 0.f;
            if (w < T4) {
                if (u >= 0 && u + 3 < T) {
                    t0 = __ldcs(xr + u);
                    t1 = __ldcs(xr + u + 1);
                    t2 = __ldcs(xr + u + 2);
                    t3 = __ldcs(xr + u + 3);
                } else {
                    if (u >= 0     && u < T)     t0 = __ldcs(xr + u);
                    if (u + 1 >= 0 && u + 1 < T) t1 = __ldcs(xr + u + 1);
                    if (u + 2 >= 0 && u + 2 < T) t2 = __ldcs(xr + u + 2);
                    if (u + 3 >= 0 && u + 3 < T) t3 = __ldcs(xr + u + 3);
                }
            }
            v[k] = make_float4(t0, t1, t2, t3);
        }
#pragma unroll
        for (int k = 0; k < VEC; ++k) {
            const int w = tile0 + threadIdx.x + k * THREADS;
            if (w < T4)
                __stcs(out4 + wbase + w, v[k]);
        }
    }
}

extern "C" void kernel_launch(void* const* d_in, const int* in_sizes, int n_in,
                              void* d_out, int out_size) {
    const float* x      = (const float*)d_in[0];
    const int*   shifts = (const int*)d_in[1];
    float4*      out4   = (float4*)d_out;

    const int rows = in_sizes[1];            // B*M = 256
    const int T    = in_sizes[0] / rows;     // 160000
    const int T4   = T / 4;                  // 40000
    const int max_shift = T / 10;            // 16000

    dim3 grid((T4 + WPB - 1) / WPB, rows);   // (40, 256)
    random_shift_kernel<<<grid, THREADS>>>(x, shifts, out4, T, max_shift);
}

// round 14
// speedup vs baseline: 1.0168x; 1.0168x over previous
#include <cuda_runtime.h>

// out[row, t] = x[row, t - s]  if 0 <= t - s < T else 0
// rows = 256, T = 160000 (T % 4 == 0), s = shifts[row] - max_shift in [-16000, 16000]
//
// R3-optimal body (VEC=4 float4 words/thread, front-batched __ldcs loads,
// __stcs stores, interior fast path, full grid) with THREADS=512 — the one
// untested configuration axis. Halves CTA count, doubles per-CTA contiguous
// DRAM footprint (32 KB windows) for better page locality. All other
// mechanisms (alignment, vector width, MLP, cache policy, residency,
// persistence, TMA) are measured-neutral at the ~74% DRAM turnaround ceiling.

#define VEC 4
#define THREADS 512
#define WPB (VEC * THREADS)   // 2048 float4 words = 8192 floats per tile

__global__ void __launch_bounds__(THREADS)
random_shift_kernel(const float* __restrict__ x,
                    const int* __restrict__ shifts,
                    float4* __restrict__ out4,
                    int T, int max_shift) {
    const int row = blockIdx.y;
    const int s = shifts[row] - max_shift;

    const int T4 = T >> 2;
    const int tile0 = blockIdx.x * WPB;                    // first word of tile
    const size_t ebase = (size_t)row * (size_t)T;          // element base
    const size_t wbase = (size_t)row * (size_t)T4;         // word base
    const float* __restrict__ xr = x + ebase;

    // tile source element range: [4*tile0 - s, 4*(tile0+WPB) - s)
    const int src_lo = 4 * tile0 - s;
    const int src_hi = 4 * (tile0 + WPB) - s;
    const bool interior = (src_lo >= 0) && (src_hi <= T) && (tile0 + WPB <= T4);

    float4 v[VEC];

    if (interior) {
#pragma unroll
        for (int k = 0; k < VEC; ++k) {
            const int u = 4 * (tile0 + (int)threadIdx.x + k * THREADS) - s;
            v[k].x = __ldcs(xr + u);
            v[k].y = __ldcs(xr + u + 1);
            v[k].z = __ldcs(xr + u + 2);
            v[k].w = __ldcs(xr + u + 3);
        }
#pragma unroll
        for (int k = 0; k < VEC; ++k) {
            const int w = tile0 + threadIdx.x + k * THREADS;
            __stcs(out4 + wbase + w, v[k]);
        }
    } else {
#pragma unroll
        for (int k = 0; k < VEC; ++k) {
            const int w = tile0 + threadIdx.x + k * THREADS;
            const int u = 4 * w - s;
            float t0 = 0.f, t1 = 0.f, t2 = 0.f, t3 = 0.f;
            if (w < T4) {
                if (u >= 0 && u + 3 < T) {
                    t0 = __ldcs(xr + u);
                    t1 = __ldcs(xr + u + 1);
                    t2 = __ldcs(xr + u + 2);
                    t3 = __ldcs(xr + u + 3);
                } else {
                    if (u >= 0     && u < T)     t0 = __ldcs(xr + u);
                    if (u + 1 >= 0 && u + 1 < T) t1 = __ldcs(xr + u + 1);
                    if (u + 2 >= 0 && u + 2 < T) t2 = __ldcs(xr + u + 2);
                    if (u + 3 >= 0 && u + 3 < T) t3 = __ldcs(xr + u + 3);
                }
            }
            v[k] = make_float4(t0, t1, t2, t3);
        }
#pragma unroll
        for (int k = 0; k < VEC; ++k) {
            const int w = tile0 + threadIdx.x + k * THREADS;
            if (w < T4)
                __stcs(out4 + wbase + w, v[k]);
        }
    }
}

extern "C" void kernel_launch(void* const* d_in, const int* in_sizes, int n_in,
                              void* d_out, int out_size) {
    const float* x      = (const float*)d_in[0];
    const int*   shifts = (const int*)d_in[1];
    float4*      out4   = (float4*)d_out;

    const int rows = in_sizes[1];            // B*M = 256
    const int T    = in_sizes[0] / rows;     // 160000
    const int T4   = T / 4;                  // 40000
    const int max_shift = T / 10;            // 16000

    dim3 grid((T4 + WPB - 1) / WPB, rows);   // (20, 256)
    random_shift_kernel<<<grid, THREADS>>>(x, shifts, out4, T, max_shift);
}